// round 1
// baseline (speedup 1.0000x reference)
#include <cuda_runtime.h>

#define BATCH 2048
#define CIN   256
#define LIN   256
#define COUT  64
#define KSZ   16
#define LOUT  61
#define FLAT  3904   // 64*61
#define H1    512
#define H2    128

// Scratch (allocation-free rule: __device__ globals)
__device__ float g_act[BATCH * FLAT];   // conv+bn+relu output, [b][co*61+l]
__device__ float g_h1[BATCH * H1];      // fc1 output

// ---------------------------------------------------------------------------
// Kernel A: Conv1d + BN + ReLU (implicit im2col GEMM)
// Block = 4 batches: M = 256 l-slots (4 x 64, 61 valid), N = 64 co, K = 4096.
// 256 threads, 8x8 micro-tile per thread. K staged in chunks of 4 ci (64 k).
// ---------------------------------------------------------------------------
__global__ __launch_bounds__(256, 2) void conv_bn_relu_kernel(
    const float* __restrict__ x,      // [2048,256,256]
    const float* __restrict__ w,      // [64,256,16]
    const float* __restrict__ cb,     // [64]
    const float* __restrict__ gamma,
    const float* __restrict__ beta,
    const float* __restrict__ mean,
    const float* __restrict__ var,
    float* __restrict__ act)
{
    __shared__ float xs[4][4][272];   // [bi][ci][t], t padded 256->272, pad zeroed
    __shared__ float ws[64 * 65];     // [(ci*16+k)*65 + co]

    const int tid = threadIdx.x;
    const int b0  = blockIdx.x * 4;
    const int lg  = tid >> 3;   // 0..31
    const int cg  = tid & 7;    // 0..7

    int bi_arr[8], off_arr[8];
#pragma unroll
    for (int i = 0; i < 8; i++) {
        int lslot  = lg + 32 * i;        // 0..255 unique per thread set
        bi_arr[i]  = lslot >> 6;         // which batch of the 4
        off_arr[i] = 4 * (lslot & 63);   // 4*lpos
    }

    float acc[8][8];
#pragma unroll
    for (int i = 0; i < 8; i++)
#pragma unroll
        for (int j = 0; j < 8; j++) acc[i][j] = 0.0f;

    for (int c0 = 0; c0 < CIN; c0 += 4) {
        __syncthreads();
        // stage x: 4 batches x 4 ci x 256 t = 4096 floats (coalesced)
#pragma unroll
        for (int i = 0; i < 16; i++) {
            int e  = tid + 256 * i;
            int bi = e >> 10;
            int ci = (e >> 8) & 3;
            int t  = e & 255;
            xs[bi][ci][t] = x[(b0 + bi) * (CIN * LIN) + (c0 + ci) * LIN + t];
        }
        // zero the tail pad [256,272): 4*4*16 = 256 entries, one per thread
        {
            int bi = tid >> 6;
            int ci = (tid >> 4) & 3;
            xs[bi][ci][256 + (tid & 15)] = 0.0f;
        }
        // stage w: 64 co x 4 ci x 16 k = 4096 floats (coalesced reads, pad-65 stores)
#pragma unroll
        for (int i = 0; i < 16; i++) {
            int e  = tid + 256 * i;
            int co = e >> 6;
            int r  = e & 63;                       // ci*16 + k
            ws[r * 65 + co] = w[co * (CIN * KSZ) + c0 * KSZ + r];
        }
        __syncthreads();

#pragma unroll 1
        for (int ci = 0; ci < 4; ci++) {
#pragma unroll 4
            for (int k = 0; k < 16; k++) {
                float bf[8];
#pragma unroll
                for (int j = 0; j < 8; j++)
                    bf[j] = ws[(ci * 16 + k) * 65 + cg + 8 * j];
#pragma unroll
                for (int i = 0; i < 8; i++) {
                    float a = xs[bi_arr[i]][ci][off_arr[i] + k];
#pragma unroll
                    for (int j = 0; j < 8; j++)
                        acc[i][j] = fmaf(a, bf[j], acc[i][j]);
                }
            }
        }
    }

    // Epilogue: fold bias + BN, ReLU, store valid l
#pragma unroll
    for (int j = 0; j < 8; j++) {
        int co = cg + 8 * j;
        float inv = gamma[co] * rsqrtf(var[co] + 1e-5f);
        float sh  = (cb[co] - mean[co]) * inv + beta[co];
#pragma unroll
        for (int i = 0; i < 8; i++) {
            int lpos = off_arr[i] >> 2;
            if (lpos < LOUT) {
                float v = fmaf(acc[i][j], inv, sh);
                act[(b0 + bi_arr[i]) * FLAT + co * LOUT + lpos] = fmaxf(v, 0.0f);
            }
        }
    }
}

// ---------------------------------------------------------------------------
// Kernel B: FC1  h1[2048,512] = act[2048,3904] @ fc1_w[512,3904]^T + fc1_b
// Tile 128(M) x 64(N), K-chunk 16, 256 threads, 8x4 micro-tile.
// ---------------------------------------------------------------------------
__global__ __launch_bounds__(256) void fc1_kernel(
    const float* __restrict__ act,
    const float* __restrict__ fw,   // [512,3904]
    const float* __restrict__ fb)   // [512]
{
    __shared__ float As[16 * 133];  // [kk][m] pad 133 (gcd(133%32=5,32)=1)
    __shared__ float Bs[16 * 69];   // [kk][n] pad 69

    const int tid = threadIdx.x;
    const int m0  = blockIdx.x * 128;
    const int n0  = blockIdx.y * 64;
    const int lg  = tid >> 4;   // 0..15
    const int cg  = tid & 15;   // 0..15

    float acc[8][4];
#pragma unroll
    for (int i = 0; i < 8; i++)
#pragma unroll
        for (int j = 0; j < 4; j++) acc[i][j] = 0.0f;

    for (int k0 = 0; k0 < FLAT; k0 += 16) {
        __syncthreads();
#pragma unroll
        for (int i = 0; i < 8; i++) {          // 128x16 = 2048
            int e = tid + 256 * i;
            int m = e >> 4, kk = e & 15;
            As[kk * 133 + m] = act[(m0 + m) * FLAT + k0 + kk];
        }
#pragma unroll
        for (int i = 0; i < 4; i++) {          // 64x16 = 1024
            int e = tid + 256 * i;
            int n = e >> 4, kk = e & 15;
            Bs[kk * 69 + n] = fw[(n0 + n) * FLAT + k0 + kk];
        }
        __syncthreads();
#pragma unroll
        for (int kk = 0; kk < 16; kk++) {
            float a[8], b[4];
#pragma unroll
            for (int i = 0; i < 8; i++) a[i] = As[kk * 133 + lg + 16 * i];
#pragma unroll
            for (int j = 0; j < 4; j++) b[j] = Bs[kk * 69 + cg + 16 * j];
#pragma unroll
            for (int i = 0; i < 8; i++)
#pragma unroll
                for (int j = 0; j < 4; j++)
                    acc[i][j] = fmaf(a[i], b[j], acc[i][j]);
        }
    }

#pragma unroll
    for (int j = 0; j < 4; j++) {
        int n = n0 + cg + 16 * j;
        float bias = fb[n];
#pragma unroll
        for (int i = 0; i < 8; i++) {
            int m = m0 + lg + 16 * i;
            g_h1[m * H1 + n] = acc[i][j] + bias;
        }
    }
}

// ---------------------------------------------------------------------------
// Kernel C: FC2 + parabit heads, writes final [2048,128,2] f32
// Tile 64(M) x 64(N), K=512 chunk 16, 256 threads, 4x4 micro-tile.
// ---------------------------------------------------------------------------
__global__ __launch_bounds__(256) void fc2_parabit_kernel(
    const float* __restrict__ fw,   // [128,512]
    const float* __restrict__ fb,   // [128]
    const float* __restrict__ bw,   // [128,2]
    const float* __restrict__ bb,   // [128,2]
    float* __restrict__ out)        // [2048,128,2]
{
    __shared__ float As[16 * 69];
    __shared__ float Bs[16 * 69];

    const int tid = threadIdx.x;
    const int m0  = blockIdx.x * 64;
    const int n0  = blockIdx.y * 64;
    const int lg  = tid >> 4;
    const int cg  = tid & 15;

    float acc[4][4];
#pragma unroll
    for (int i = 0; i < 4; i++)
#pragma unroll
        for (int j = 0; j < 4; j++) acc[i][j] = 0.0f;

    for (int k0 = 0; k0 < H1; k0 += 16) {
        __syncthreads();
#pragma unroll
        for (int i = 0; i < 4; i++) {          // 64x16 = 1024
            int e = tid + 256 * i;
            int m = e >> 4, kk = e & 15;
            As[kk * 69 + m] = g_h1[(m0 + m) * H1 + k0 + kk];
        }
#pragma unroll
        for (int i = 0; i < 4; i++) {
            int e = tid + 256 * i;
            int n = e >> 4, kk = e & 15;
            Bs[kk * 69 + n] = fw[(n0 + n) * H1 + k0 + kk];
        }
        __syncthreads();
#pragma unroll
        for (int kk = 0; kk < 16; kk++) {
            float a[4], b[4];
#pragma unroll
            for (int i = 0; i < 4; i++) a[i] = As[kk * 69 + lg + 16 * i];
#pragma unroll
            for (int j = 0; j < 4; j++) b[j] = Bs[kk * 69 + cg + 16 * j];
#pragma unroll
            for (int i = 0; i < 4; i++)
#pragma unroll
                for (int j = 0; j < 4; j++)
                    acc[i][j] = fmaf(a[i], b[j], acc[i][j]);
        }
    }

#pragma unroll
    for (int j = 0; j < 4; j++) {
        int n = n0 + cg + 16 * j;
        float bias = fb[n];
        float w0 = bw[n * 2 + 0], w1 = bw[n * 2 + 1];
        float c0 = bb[n * 2 + 0], c1 = bb[n * 2 + 1];
#pragma unroll
        for (int i = 0; i < 4; i++) {
            int m = m0 + lg + 16 * i;
            float v = acc[i][j] + bias;
            int o = (m * H2 + n) * 2;
            out[o + 0] = fmaf(v, w0, c0);
            out[o + 1] = fmaf(v, w1, c1);
        }
    }
}

// ---------------------------------------------------------------------------
extern "C" void kernel_launch(void* const* d_in, const int* in_sizes, int n_in,
                              void* d_out, int out_size)
{
    const float* x       = (const float*)d_in[0];   // [2048,256,256]
    const float* conv_w  = (const float*)d_in[1];   // [64,256,16]
    const float* conv_b  = (const float*)d_in[2];   // [64]
    const float* bn_g    = (const float*)d_in[3];
    const float* bn_b    = (const float*)d_in[4];
    const float* bn_m    = (const float*)d_in[5];
    const float* bn_v    = (const float*)d_in[6];
    const float* fc1_w   = (const float*)d_in[7];   // [512,3904]
    const float* fc1_b   = (const float*)d_in[8];
    const float* fc2_w   = (const float*)d_in[9];   // [128,512]
    const float* fc2_b   = (const float*)d_in[10];
    const float* bit_w   = (const float*)d_in[11];  // [128,2]
    const float* bit_b   = (const float*)d_in[12];  // [128,2]
    float* out = (float*)d_out;                     // [2048,128,2]

    float* act_ptr = nullptr;
    cudaGetSymbolAddress((void**)&act_ptr, g_act);

    conv_bn_relu_kernel<<<BATCH / 4, 256>>>(x, conv_w, conv_b, bn_g, bn_b, bn_m, bn_v, act_ptr);
    fc1_kernel<<<dim3(BATCH / 128, H1 / 64), 256>>>(act_ptr, fc1_w, fc1_b);
    fc2_parabit_kernel<<<dim3(BATCH / 64, H2 / 64), 256>>>(fc2_w, fc2_b, bit_w, bit_b, out);
}

// round 3
// speedup vs baseline: 1.0002x; 1.0002x over previous
#include <cuda_runtime.h>

#define BATCH 2048
#define CIN   256
#define LIN   256
#define COUT  64
#define KSZ   16
#define LOUT  61
#define FLAT  3904   // 64*61
#define H1    512
#define H2    128

// Scratch (allocation-free rule: __device__ globals)
__device__ float g_act[BATCH * FLAT];   // conv+bn+relu output, [b][co*61+l]
__device__ float g_h1[BATCH * H1];      // fc1 output

// ---------------------------------------------------------------------------
// Kernel A: Conv1d + BN + ReLU (implicit im2col GEMM)
// Block = 4 batches: M = 256 l-slots (4 x 64, 61 valid), N = 64 co, K = 4096.
// 256 threads, 8x8 micro-tile per thread. K staged in chunks of 4 ci (64 k).
// ---------------------------------------------------------------------------
__global__ __launch_bounds__(256, 2) void conv_bn_relu_kernel(
    const float* __restrict__ x,      // [2048,256,256]
    const float* __restrict__ w,      // [64,256,16]
    const float* __restrict__ cb,     // [64]
    const float* __restrict__ gamma,
    const float* __restrict__ beta,
    const float* __restrict__ mean,
    const float* __restrict__ var,
    float* __restrict__ act)
{
    __shared__ float xs[4][4][272];   // [bi][ci][t], t padded 256->272, pad zeroed
    __shared__ float ws[64 * 65];     // [(ci*16+k)*65 + co]

    const int tid = threadIdx.x;
    const int b0  = blockIdx.x * 4;
    const int lg  = tid >> 3;   // 0..31
    const int cg  = tid & 7;    // 0..7

    int bi_arr[8], off_arr[8];
#pragma unroll
    for (int i = 0; i < 8; i++) {
        int lslot  = lg + 32 * i;        // 0..255 unique per thread set
        bi_arr[i]  = lslot >> 6;         // which batch of the 4
        off_arr[i] = 4 * (lslot & 63);   // 4*lpos
    }

    float acc[8][8];
#pragma unroll
    for (int i = 0; i < 8; i++)
#pragma unroll
        for (int j = 0; j < 8; j++) acc[i][j] = 0.0f;

    for (int c0 = 0; c0 < CIN; c0 += 4) {
        __syncthreads();
        // stage x: 4 batches x 4 ci x 256 t = 4096 floats (coalesced)
#pragma unroll
        for (int i = 0; i < 16; i++) {
            int e  = tid + 256 * i;
            int bi = e >> 10;
            int ci = (e >> 8) & 3;
            int t  = e & 255;
            xs[bi][ci][t] = x[(b0 + bi) * (CIN * LIN) + (c0 + ci) * LIN + t];
        }
        // zero the tail pad [256,272): 4*4*16 = 256 entries, one per thread
        {
            int bi = tid >> 6;
            int ci = (tid >> 4) & 3;
            xs[bi][ci][256 + (tid & 15)] = 0.0f;
        }
        // stage w: 64 co x 4 ci x 16 k = 4096 floats (coalesced reads, pad-65 stores)
#pragma unroll
        for (int i = 0; i < 16; i++) {
            int e  = tid + 256 * i;
            int co = e >> 6;
            int r  = e & 63;                       // ci*16 + k
            ws[r * 65 + co] = w[co * (CIN * KSZ) + c0 * KSZ + r];
        }
        __syncthreads();

#pragma unroll 1
        for (int ci = 0; ci < 4; ci++) {
#pragma unroll 4
            for (int k = 0; k < 16; k++) {
                float bf[8];
#pragma unroll
                for (int j = 0; j < 8; j++)
                    bf[j] = ws[(ci * 16 + k) * 65 + cg + 8 * j];
#pragma unroll
                for (int i = 0; i < 8; i++) {
                    float a = xs[bi_arr[i]][ci][off_arr[i] + k];
#pragma unroll
                    for (int j = 0; j < 8; j++)
                        acc[i][j] = fmaf(a, bf[j], acc[i][j]);
                }
            }
        }
    }

    // Epilogue: fold bias + BN, ReLU, store valid l
#pragma unroll
    for (int j = 0; j < 8; j++) {
        int co = cg + 8 * j;
        float inv = gamma[co] * rsqrtf(var[co] + 1e-5f);
        float sh  = (cb[co] - mean[co]) * inv + beta[co];
#pragma unroll
        for (int i = 0; i < 8; i++) {
            int lpos = off_arr[i] >> 2;
            if (lpos < LOUT) {
                float v = fmaf(acc[i][j], inv, sh);
                act[(b0 + bi_arr[i]) * FLAT + co * LOUT + lpos] = fmaxf(v, 0.0f);
            }
        }
    }
}

// ---------------------------------------------------------------------------
// Kernel B: FC1  h1[2048,512] = act[2048,3904] @ fc1_w[512,3904]^T + fc1_b
// Tile 128(M) x 64(N), K-chunk 16, 256 threads, 8x4 micro-tile.
// ---------------------------------------------------------------------------
__global__ __launch_bounds__(256) void fc1_kernel(
    const float* __restrict__ act,
    const float* __restrict__ fw,   // [512,3904]
    const float* __restrict__ fb)   // [512]
{
    __shared__ float As[16 * 133];  // [kk][m] pad 133 (gcd(133%32=5,32)=1)
    __shared__ float Bs[16 * 69];   // [kk][n] pad 69

    const int tid = threadIdx.x;
    const int m0  = blockIdx.x * 128;
    const int n0  = blockIdx.y * 64;
    const int lg  = tid >> 4;   // 0..15
    const int cg  = tid & 15;   // 0..15

    float acc[8][4];
#pragma unroll
    for (int i = 0; i < 8; i++)
#pragma unroll
        for (int j = 0; j < 4; j++) acc[i][j] = 0.0f;

    for (int k0 = 0; k0 < FLAT; k0 += 16) {
        __syncthreads();
#pragma unroll
        for (int i = 0; i < 8; i++) {          // 128x16 = 2048
            int e = tid + 256 * i;
            int m = e >> 4, kk = e & 15;
            As[kk * 133 + m] = act[(m0 + m) * FLAT + k0 + kk];
        }
#pragma unroll
        for (int i = 0; i < 4; i++) {          // 64x16 = 1024
            int e = tid + 256 * i;
            int n = e >> 4, kk = e & 15;
            Bs[kk * 69 + n] = fw[(n0 + n) * FLAT + k0 + kk];
        }
        __syncthreads();
#pragma unroll
        for (int kk = 0; kk < 16; kk++) {
            float a[8], b[4];
#pragma unroll
            for (int i = 0; i < 8; i++) a[i] = As[kk * 133 + lg + 16 * i];
#pragma unroll
            for (int j = 0; j < 4; j++) b[j] = Bs[kk * 69 + cg + 16 * j];
#pragma unroll
            for (int i = 0; i < 8; i++)
#pragma unroll
                for (int j = 0; j < 4; j++)
                    acc[i][j] = fmaf(a[i], b[j], acc[i][j]);
        }
    }

#pragma unroll
    for (int j = 0; j < 4; j++) {
        int n = n0 + cg + 16 * j;
        float bias = fb[n];
#pragma unroll
        for (int i = 0; i < 8; i++) {
            int m = m0 + lg + 16 * i;
            g_h1[m * H1 + n] = acc[i][j] + bias;
        }
    }
}

// ---------------------------------------------------------------------------
// Kernel C: FC2 + parabit heads, writes final [2048,128,2] f32
// Tile 64(M) x 64(N), K=512 chunk 16, 256 threads, 4x4 micro-tile.
// ---------------------------------------------------------------------------
__global__ __launch_bounds__(256) void fc2_parabit_kernel(
    const float* __restrict__ fw,   // [128,512]
    const float* __restrict__ fb,   // [128]
    const float* __restrict__ bw,   // [128,2]
    const float* __restrict__ bb,   // [128,2]
    float* __restrict__ out)        // [2048,128,2]
{
    __shared__ float As[16 * 69];
    __shared__ float Bs[16 * 69];

    const int tid = threadIdx.x;
    const int m0  = blockIdx.x * 64;
    const int n0  = blockIdx.y * 64;
    const int lg  = tid >> 4;
    const int cg  = tid & 15;

    float acc[4][4];
#pragma unroll
    for (int i = 0; i < 4; i++)
#pragma unroll
        for (int j = 0; j < 4; j++) acc[i][j] = 0.0f;

    for (int k0 = 0; k0 < H1; k0 += 16) {
        __syncthreads();
#pragma unroll
        for (int i = 0; i < 4; i++) {          // 64x16 = 1024
            int e = tid + 256 * i;
            int m = e >> 4, kk = e & 15;
            As[kk * 69 + m] = g_h1[(m0 + m) * H1 + k0 + kk];
        }
#pragma unroll
        for (int i = 0; i < 4; i++) {
            int e = tid + 256 * i;
            int n = e >> 4, kk = e & 15;
            Bs[kk * 69 + n] = fw[(n0 + n) * H1 + k0 + kk];
        }
        __syncthreads();
#pragma unroll
        for (int kk = 0; kk < 16; kk++) {
            float a[4], b[4];
#pragma unroll
            for (int i = 0; i < 4; i++) a[i] = As[kk * 69 + lg + 16 * i];
#pragma unroll
            for (int j = 0; j < 4; j++) b[j] = Bs[kk * 69 + cg + 16 * j];
#pragma unroll
            for (int i = 0; i < 4; i++)
#pragma unroll
                for (int j = 0; j < 4; j++)
                    acc[i][j] = fmaf(a[i], b[j], acc[i][j]);
        }
    }

#pragma unroll
    for (int j = 0; j < 4; j++) {
        int n = n0 + cg + 16 * j;
        float bias = fb[n];
        float w0 = bw[n * 2 + 0], w1 = bw[n * 2 + 1];
        float c0 = bb[n * 2 + 0], c1 = bb[n * 2 + 1];
#pragma unroll
        for (int i = 0; i < 4; i++) {
            int m = m0 + lg + 16 * i;
            float v = acc[i][j] + bias;
            int o = (m * H2 + n) * 2;
            out[o + 0] = fmaf(v, w0, c0);
            out[o + 1] = fmaf(v, w1, c1);
        }
    }
}

// ---------------------------------------------------------------------------
extern "C" void kernel_launch(void* const* d_in, const int* in_sizes, int n_in,
                              void* d_out, int out_size)
{
    const float* x       = (const float*)d_in[0];   // [2048,256,256]
    const float* conv_w  = (const float*)d_in[1];   // [64,256,16]
    const float* conv_b  = (const float*)d_in[2];   // [64]
    const float* bn_g    = (const float*)d_in[3];
    const float* bn_b    = (const float*)d_in[4];
    const float* bn_m    = (const float*)d_in[5];
    const float* bn_v    = (const float*)d_in[6];
    const float* fc1_w   = (const float*)d_in[7];   // [512,3904]
    const float* fc1_b   = (const float*)d_in[8];
    const float* fc2_w   = (const float*)d_in[9];   // [128,512]
    const float* fc2_b   = (const float*)d_in[10];
    const float* bit_w   = (const float*)d_in[11];  // [128,2]
    const float* bit_b   = (const float*)d_in[12];  // [128,2]
    float* out = (float*)d_out;                     // [2048,128,2]

    float* act_ptr = nullptr;
    cudaGetSymbolAddress((void**)&act_ptr, g_act);

    conv_bn_relu_kernel<<<BATCH / 4, 256>>>(x, conv_w, conv_b, bn_g, bn_b, bn_m, bn_v, act_ptr);
    fc1_kernel<<<dim3(BATCH / 128, H1 / 64), 256>>>(act_ptr, fc1_w, fc1_b);
    fc2_parabit_kernel<<<dim3(BATCH / 64, H2 / 64), 256>>>(fc2_w, fc2_b, bit_w, bit_b, out);
}

// round 6
// speedup vs baseline: 7.5850x; 7.5836x over previous
#include <cuda_runtime.h>
#include <cuda_fp16.h>
#include <stdint.h>

#define BATCH 2048
#define CIN   256
#define LIN   256
#define COUT  64
#define LOUT  61
#define FLAT  3904   // permuted k' = l*64 + co
#define H1    512
#define H2    128

// ---------------- device-global scratch (allocation-free rule) ----------------
__device__ __half g_WcH[COUT * 4096];                 // BN-folded conv weights fp16
__device__ float  g_bshift[COUT];
__device__ __half g_actH[(size_t)BATCH * FLAT];       // conv output fp16, [b][l*64+co]
__device__ __half g_W12h[H2 * FLAT];                  // fused fc2@fc1 weights fp16, [n][k']
__device__ float  g_b12[H2];
__device__ float  g_part[8 * (size_t)BATCH * H2];     // split-K partials

// ---------------- helpers ----------------
__device__ __forceinline__ uint32_t packh2(float a, float b) {
    __half2 h = __floats2half2_rn(a, b);
    return *reinterpret_cast<uint32_t*>(&h);
}
__device__ __forceinline__ void mma16816(float* d, const uint32_t* a, const uint32_t* b) {
    asm volatile("mma.sync.aligned.m16n8k16.row.col.f32.f16.f16.f32 "
                 "{%0,%1,%2,%3}, {%4,%5,%6,%7}, {%8,%9}, {%0,%1,%2,%3};"
                 : "+f"(d[0]), "+f"(d[1]), "+f"(d[2]), "+f"(d[3])
                 : "r"(a[0]), "r"(a[1]), "r"(a[2]), "r"(a[3]), "r"(b[0]), "r"(b[1]));
}

// ===========================================================================
// prep_split: fold BN into conv weights -> fp16; compute bshift.
// ===========================================================================
__global__ void prep_split(const float* __restrict__ cw, const float* __restrict__ cb,
                           const float* __restrict__ gam, const float* __restrict__ bet,
                           const float* __restrict__ mn, const float* __restrict__ vr)
{
    int gid = blockIdx.x * blockDim.x + threadIdx.x;
    int stride = gridDim.x * blockDim.x;
    for (int i = gid; i < COUT * 4096; i += stride) {
        int co = i >> 12;
        float inv = gam[co] * rsqrtf(vr[co] + 1e-5f);
        g_WcH[i] = __float2half_rn(cw[i] * inv);
    }
    if (gid < COUT) {
        float inv = gam[gid] * rsqrtf(vr[gid] + 1e-5f);
        g_bshift[gid] = (cb[gid] - mn[gid]) * inv + bet[gid];
    }
}

// ===========================================================================
// prep_b12: b12[n] = fc2_b[n] + sum_h fc2_w[n,h]*fc1_b[h].  One warp per n.
// ===========================================================================
__global__ void prep_b12(const float* __restrict__ w2, const float* __restrict__ b1,
                         const float* __restrict__ b2)
{
    int wid = (blockIdx.x * blockDim.x + threadIdx.x) >> 5;
    int lane = threadIdx.x & 31;
    if (wid >= H2) return;
    float s = 0.0f;
    for (int h = lane; h < H1; h += 32) s += w2[wid * H1 + h] * b1[h];
#pragma unroll
    for (int o = 16; o > 0; o >>= 1) s += __shfl_xor_sync(0xFFFFFFFF, s, o);
    if (lane == 0) g_b12[wid] = b2[wid] + s;
}

// ===========================================================================
// prep_gemm: W12[n][k'=l*64+co] = sum_h fc2_w[n,h] * fc1_w[h, co*61+l].
// Grid = 61 (one CTA per l). M=128(n), N=64(co), K=512 (8 chunks of 64 h).
// 8 warps 4Mx2N, warp tile 32x32.
// ===========================================================================
__global__ __launch_bounds__(256) void prep_gemm(const float* __restrict__ w2,
                                                 const float* __restrict__ w1)
{
    __shared__ uint32_t As[128 * 36];   // [n][hp] half2, row pad 36 words
    __shared__ uint32_t Bs[64 * 36];    // [co][hp]

    const int tid = threadIdx.x, wid = tid >> 5, lane = tid & 31;
    const int g = lane >> 2, tig = lane & 3;
    const int mbase = (wid >> 1) * 32, nb = (wid & 1) * 32;
    const int l = blockIdx.x;

    float acc[2][4][4];
#pragma unroll
    for (int a = 0; a < 2; a++)
#pragma unroll
        for (int b = 0; b < 4; b++)
#pragma unroll
            for (int c2 = 0; c2 < 4; c2++) acc[a][b][c2] = 0.0f;

    for (int c = 0; c < 8; c++) {
        __syncthreads();
        // stage A = fc2_w[n][h chunk]: 128 x 32 half2
#pragma unroll
        for (int i = 0; i < 16; i++) {
            int u = tid + 256 * i;      // 0..4095
            int n = u >> 5, hp = u & 31;
            float2 v = *(const float2*)(w2 + n * H1 + c * 64 + 2 * hp);
            As[n * 36 + hp] = packh2(v.x, v.y);
        }
        // stage B[co][h] from strided fc1_w
#pragma unroll
        for (int i = 0; i < 8; i++) {
            int u = tid + 256 * i;      // 0..2047
            int co = u >> 5, hp = u & 31;
            int h = c * 64 + 2 * hp;
            float f0 = w1[(size_t)h * FLAT + co * 61 + l];
            float f1 = w1[(size_t)(h + 1) * FLAT + co * 61 + l];
            Bs[co * 36 + hp] = packh2(f0, f1);
        }
        __syncthreads();
#pragma unroll
        for (int ks = 0; ks < 4; ks++) {
            uint32_t A[2][4], B[4][2];
#pragma unroll
            for (int mf = 0; mf < 2; mf++) {
                int r = mbase + 16 * mf + g;
                int wd = r * 36 + ks * 8 + tig;
                A[mf][0] = As[wd];          A[mf][1] = As[wd + 8 * 36];
                A[mf][2] = As[wd + 4];      A[mf][3] = As[wd + 8 * 36 + 4];
            }
#pragma unroll
            for (int nf = 0; nf < 4; nf++) {
                int n = nb + 8 * nf + g;
                int wd = n * 36 + ks * 8 + tig;
                B[nf][0] = Bs[wd]; B[nf][1] = Bs[wd + 4];
            }
#pragma unroll
            for (int mf = 0; mf < 2; mf++)
#pragma unroll
                for (int nf = 0; nf < 4; nf++)
                    mma16816(acc[mf][nf], A[mf], B[nf]);
        }
    }
    // epilogue: store fp16 W12
#pragma unroll
    for (int nf = 0; nf < 4; nf++) {
        int c0 = nb + 8 * nf + 2 * tig;          // local k' (co)
#pragma unroll
        for (int mf = 0; mf < 2; mf++) {
            int r = mbase + 16 * mf + g;
            *(uint32_t*)(g_W12h + (size_t)r * FLAT + l * 64 + c0) =
                packh2(acc[mf][nf][0], acc[mf][nf][1]);
            *(uint32_t*)(g_W12h + (size_t)(r + 8) * FLAT + l * 64 + c0) =
                packh2(acc[mf][nf][2], acc[mf][nf][3]);
        }
    }
}

// ===========================================================================
// conv_mma: Conv1d+BN+ReLU as implicit-im2col HMMA GEMM.
// CTA = 2 batches: M=128 (bi*64+lp, lp<61 valid), N=64 (co), K=4096.
// Chunks of 64 k (4 ci x 16). 8 warps 4Mx2N, warp tile 32x32.
// x staged as half2 pairs (t even): fragment k-pairs always hit even t.
// ===========================================================================
#define XS_ROW 136
__global__ __launch_bounds__(256, 2) void conv_mma(const float* __restrict__ x)
{
    __shared__ uint32_t xs[8 * XS_ROW];   // [bi*4+ci][te] half2
    __shared__ uint32_t bs[64 * 36];      // [co][kwd] half2 (kwd = kk/2, 0..31)

    const int tid = threadIdx.x, wid = tid >> 5, lane = tid & 31;
    const int g = lane >> 2, tig = lane & 3;
    const int mbase = (wid >> 1) * 32, nb = (wid & 1) * 32;
    const int b0 = blockIdx.x * 2;

    float acc[2][4][4];
#pragma unroll
    for (int a = 0; a < 2; a++)
#pragma unroll
        for (int b = 0; b < 4; b++)
#pragma unroll
            for (int c2 = 0; c2 < 4; c2++) acc[a][b][c2] = 0.0f;

    float4 xv[2];
    uint4  wv[2];
    // prefetch chunk 0
#pragma unroll
    for (int r = 0; r < 2; r++) {
        int e = tid + 256 * r;
        int bi = e >> 8, ci = (e >> 6) & 3, t4 = (e & 63) << 2;
        xv[r] = *(const float4*)(x + ((size_t)(b0 + bi) << 16) + ((0 * 4 + ci) << 8) + t4);
        int u = tid + 256 * r;
        int co = u >> 3, q = u & 7;
        wv[r] = *(const uint4*)(g_WcH + co * 4096 + 0 * 64 + q * 8);
    }

    for (int c = 0; c < 64; c++) {
        __syncthreads();
        // store staged regs -> smem
#pragma unroll
        for (int r = 0; r < 2; r++) {
            int e = tid + 256 * r;
            int bi = e >> 8, ci = (e >> 6) & 3, t4 = (e & 63) << 2;
            int wb = (bi * 4 + ci) * XS_ROW + (t4 >> 1);
            xs[wb]     = packh2(xv[r].x, xv[r].y);
            xs[wb + 1] = packh2(xv[r].z, xv[r].w);
            int u = tid + 256 * r;
            int co = u >> 3, q = u & 7;
            *(uint4*)&bs[co * 36 + q * 4] = wv[r];
        }
        __syncthreads();
        // prefetch next chunk
        if (c < 63) {
#pragma unroll
            for (int r = 0; r < 2; r++) {
                int e = tid + 256 * r;
                int bi = e >> 8, ci = (e >> 6) & 3, t4 = (e & 63) << 2;
                xv[r] = *(const float4*)(x + ((size_t)(b0 + bi) << 16) + (((c + 1) * 4 + ci) << 8) + t4);
                int u = tid + 256 * r;
                int co = u >> 3, q = u & 7;
                wv[r] = *(const uint4*)(g_WcH + co * 4096 + (c + 1) * 64 + q * 8);
            }
        }
        // math
#pragma unroll
        for (int ks = 0; ks < 4; ks++) {         // ks == ci within chunk
            uint32_t A[2][4], B[4][2];
#pragma unroll
            for (int mf = 0; mf < 2; mf++) {
                int r = mbase + 16 * mf + g;
                int xb = ((r >> 6) * 4 + ks) * XS_ROW + 2 * (r & 63) + tig;
                A[mf][0] = xs[xb];        A[mf][1] = xs[xb + 16];
                A[mf][2] = xs[xb + 4];    A[mf][3] = xs[xb + 20];
            }
#pragma unroll
            for (int nf = 0; nf < 4; nf++) {
                int n = nb + 8 * nf + g;
                int wd = n * 36 + ks * 8 + tig;
                B[nf][0] = bs[wd]; B[nf][1] = bs[wd + 4];
            }
#pragma unroll
            for (int mf = 0; mf < 2; mf++)
#pragma unroll
                for (int nf = 0; nf < 4; nf++)
                    mma16816(acc[mf][nf], A[mf], B[nf]);
        }
    }

    // epilogue: bias/BN shift + ReLU + fp16 store (permuted k' = lp*64+co)
#pragma unroll
    for (int nf = 0; nf < 4; nf++) {
        int co0 = nb + 8 * nf + 2 * tig;
        float s0 = g_bshift[co0], s1 = g_bshift[co0 + 1];
#pragma unroll
        for (int mf = 0; mf < 2; mf++) {
            int r = mbase + 16 * mf + g;
            int bi = r >> 6, lp = r & 63;
            if (lp < 61) {
                *(uint32_t*)(g_actH + (size_t)(b0 + bi) * FLAT + lp * 64 + co0) =
                    packh2(fmaxf(acc[mf][nf][0] + s0, 0.0f),
                           fmaxf(acc[mf][nf][1] + s1, 0.0f));
            }
            int r2 = r + 8;
            int bi2 = r2 >> 6, lp2 = r2 & 63;
            if (lp2 < 61) {
                *(uint32_t*)(g_actH + (size_t)(b0 + bi2) * FLAT + lp2 * 64 + co0) =
                    packh2(fmaxf(acc[mf][nf][2] + s0, 0.0f),
                           fmaxf(acc[mf][nf][3] + s1, 0.0f));
            }
        }
    }
}

// ===========================================================================
// fc_part: split-K fused FC.  out_part[ks][b][n] = act[b,:] . W12[n,:] (K slice)
// Grid (16 m-tiles, 8 k-splits). M=128, N=128. 8 warps 4Mx2N, warp 32x64.
// ===========================================================================
__global__ __launch_bounds__(256, 2) void fc_part()
{
    __shared__ uint32_t As[128 * 36];
    __shared__ uint32_t Bs[128 * 36];

    const int tid = threadIdx.x, wid = tid >> 5, lane = tid & 31;
    const int g = lane >> 2, tig = lane & 3;
    const int mbase = (wid >> 1) * 32, nbase = (wid & 1) * 64;
    const int m0 = blockIdx.x * 128;
    const int ksp = blockIdx.y;
    const int cb = (61 * ksp) / 8, ce = (61 * (ksp + 1)) / 8;

    float acc[2][8][4];
#pragma unroll
    for (int a = 0; a < 2; a++)
#pragma unroll
        for (int b = 0; b < 8; b++)
#pragma unroll
            for (int c2 = 0; c2 < 4; c2++) acc[a][b][c2] = 0.0f;

    for (int c = cb; c < ce; c++) {
        __syncthreads();
#pragma unroll
        for (int i = 0; i < 4; i++) {
            int u = tid + 256 * i;        // 0..1023
            int row = u >> 3, q = u & 7;
            uint4 av = *(const uint4*)(g_actH + (size_t)(m0 + row) * FLAT + c * 64 + q * 8);
            uint4 bv = *(const uint4*)(g_W12h + (size_t)row * FLAT + c * 64 + q * 8);
            *(uint4*)&As[row * 36 + q * 4] = av;
            *(uint4*)&Bs[row * 36 + q * 4] = bv;
        }
        __syncthreads();
#pragma unroll
        for (int ks = 0; ks < 4; ks++) {
            uint32_t A[2][4], B[8][2];
#pragma unroll
            for (int mf = 0; mf < 2; mf++) {
                int r = mbase + 16 * mf + g;
                int wd = r * 36 + ks * 8 + tig;
                A[mf][0] = As[wd];       A[mf][1] = As[wd + 8 * 36];
                A[mf][2] = As[wd + 4];   A[mf][3] = As[wd + 8 * 36 + 4];
            }
#pragma unroll
            for (int nf = 0; nf < 8; nf++) {
                int n = nbase + 8 * nf + g;
                int wd = n * 36 + ks * 8 + tig;
                B[nf][0] = Bs[wd]; B[nf][1] = Bs[wd + 4];
            }
#pragma unroll
            for (int mf = 0; mf < 2; mf++)
#pragma unroll
                for (int nf = 0; nf < 8; nf++)
                    mma16816(acc[mf][nf], A[mf], B[nf]);
        }
    }
#pragma unroll
    for (int nf = 0; nf < 8; nf++) {
        int c0 = nbase + 8 * nf + 2 * tig;
#pragma unroll
        for (int mf = 0; mf < 2; mf++) {
            int r = mbase + 16 * mf + g;
            *(float2*)(g_part + ((size_t)ksp * BATCH + m0 + r) * H2 + c0) =
                make_float2(acc[mf][nf][0], acc[mf][nf][1]);
            *(float2*)(g_part + ((size_t)ksp * BATCH + m0 + r + 8) * H2 + c0) =
                make_float2(acc[mf][nf][2], acc[mf][nf][3]);
        }
    }
}

// ===========================================================================
// fc_reduce: sum split-K partials + b12, apply parabit heads, write out.
// ===========================================================================
__global__ void fc_reduce(const float* __restrict__ bw, const float* __restrict__ bb,
                          float* __restrict__ out)
{
    int idx = blockIdx.x * blockDim.x + threadIdx.x;   // b*128 + n
    int n = idx & 127;
    float s = g_b12[n];
#pragma unroll
    for (int ks = 0; ks < 8; ks++)
        s += g_part[(size_t)ks * BATCH * H2 + idx];
    float2 o = make_float2(fmaf(s, bw[2 * n], bb[2 * n]),
                           fmaf(s, bw[2 * n + 1], bb[2 * n + 1]));
    *(float2*)(out + (size_t)idx * 2) = o;
}

// ===========================================================================
extern "C" void kernel_launch(void* const* d_in, const int* in_sizes, int n_in,
                              void* d_out, int out_size)
{
    const float* x      = (const float*)d_in[0];
    const float* conv_w = (const float*)d_in[1];
    const float* conv_b = (const float*)d_in[2];
    const float* bn_g   = (const float*)d_in[3];
    const float* bn_b   = (const float*)d_in[4];
    const float* bn_m   = (const float*)d_in[5];
    const float* bn_v   = (const float*)d_in[6];
    const float* fc1_w  = (const float*)d_in[7];
    const float* fc1_b  = (const float*)d_in[8];
    const float* fc2_w  = (const float*)d_in[9];
    const float* fc2_b  = (const float*)d_in[10];
    const float* bit_w  = (const float*)d_in[11];
    const float* bit_b  = (const float*)d_in[12];
    float* out = (float*)d_out;

    prep_split<<<256, 256>>>(conv_w, conv_b, bn_g, bn_b, bn_m, bn_v);
    prep_b12<<<16, 256>>>(fc2_w, fc1_b, fc2_b);
    prep_gemm<<<61, 256>>>(fc2_w, fc1_w);
    conv_mma<<<BATCH / 2, 256>>>(x);
    fc_part<<<dim3(16, 8), 256>>>();
    fc_reduce<<<BATCH * H2 / 256, 256>>>(bit_w, bit_b, out);
}

// round 7
// speedup vs baseline: 8.6738x; 1.1436x over previous
#include <cuda_runtime.h>
#include <cuda_fp16.h>
#include <stdint.h>

#define BATCH 2048
#define CIN   256
#define LIN   256
#define COUT  64
#define LOUT  61
#define FLAT  3904   // permuted k' = l*64 + co
#define H1    512
#define H2    128

// ---------------- device-global scratch (allocation-free rule) ----------------
__device__ __half g_WcH[COUT * 4096];                 // BN-folded conv weights fp16
__device__ float  g_bshift[COUT];
__device__ __half g_actH[(size_t)BATCH * FLAT];       // conv output fp16, [b][l*64+co]
__device__ __half g_W1t[(size_t)FLAT * H1];           // fc1 w transposed: [k'][h] fp16
__device__ __half g_W12h[H2 * FLAT];                  // fused fc2@fc1 weights fp16, [n][k']
__device__ float  g_b12[H2];
__device__ float  g_part[8 * (size_t)BATCH * H2];     // split-K partials

// ---------------- helpers ----------------
__device__ __forceinline__ uint32_t packh2(float a, float b) {
    __half2 h = __floats2half2_rn(a, b);
    return *reinterpret_cast<uint32_t*>(&h);
}
__device__ __forceinline__ void mma16816(float* d, const uint32_t* a, const uint32_t* b) {
    asm volatile("mma.sync.aligned.m16n8k16.row.col.f32.f16.f16.f32 "
                 "{%0,%1,%2,%3}, {%4,%5,%6,%7}, {%8,%9}, {%0,%1,%2,%3};"
                 : "+f"(d[0]), "+f"(d[1]), "+f"(d[2]), "+f"(d[3])
                 : "r"(a[0]), "r"(a[1]), "r"(a[2]), "r"(a[3]), "r"(b[0]), "r"(b[1]));
}
__device__ __forceinline__ void ldsm4(uint32_t* r, uint32_t addr) {
    asm volatile("ldmatrix.sync.aligned.m8n8.x4.shared.b16 {%0,%1,%2,%3}, [%4];"
                 : "=r"(r[0]), "=r"(r[1]), "=r"(r[2]), "=r"(r[3]) : "r"(addr));
}
__device__ __forceinline__ uint32_t cvta_sm(const void* p) {
    uint32_t a;
    asm("{ .reg .u64 t; cvta.to.shared.u64 t, %1; cvt.u32.u64 %0, t; }" : "=r"(a) : "l"(p));
    return a;
}

// ===========================================================================
// prep_split: fold BN into conv weights -> fp16; compute bshift.
// ===========================================================================
__global__ void prep_split(const float* __restrict__ cw, const float* __restrict__ cb,
                           const float* __restrict__ gam, const float* __restrict__ bet,
                           const float* __restrict__ mn, const float* __restrict__ vr)
{
    int gid = blockIdx.x * blockDim.x + threadIdx.x;
    int stride = gridDim.x * blockDim.x;
    for (int i = gid; i < COUT * 4096; i += stride) {
        int co = i >> 12;
        float inv = gam[co] * rsqrtf(vr[co] + 1e-5f);
        g_WcH[i] = __float2half_rn(cw[i] * inv);
    }
    if (gid < COUT) {
        float inv = gam[gid] * rsqrtf(vr[gid] + 1e-5f);
        g_bshift[gid] = (cb[gid] - mn[gid]) * inv + bet[gid];
    }
}

// ===========================================================================
// prep_b12: b12[n] = fc2_b[n] + sum_h fc2_w[n,h]*fc1_b[h].
// ===========================================================================
__global__ void prep_b12(const float* __restrict__ w2, const float* __restrict__ b1,
                         const float* __restrict__ b2)
{
    int wid = (blockIdx.x * blockDim.x + threadIdx.x) >> 5;
    int lane = threadIdx.x & 31;
    if (wid >= H2) return;
    float s = 0.0f;
    for (int h = lane; h < H1; h += 32) s += w2[wid * H1 + h] * b1[h];
#pragma unroll
    for (int o = 16; o > 0; o >>= 1) s += __shfl_xor_sync(0xFFFFFFFF, s, o);
    if (lane == 0) g_b12[wid] = b2[wid] + s;
}

// ===========================================================================
// transpose_w1: g_W1t[(l*64+co)][h] = fp16(fc1_w[h][co*61+l]).  Grid 64 x 4.
// ===========================================================================
__global__ __launch_bounds__(256) void transpose_w1(const float* __restrict__ w1)
{
    __shared__ float s[128][65];
    const int co = blockIdx.x, hb = blockIdx.y;
    const int tid = threadIdx.x;
    {
        int lid = tid & 63, rid = tid >> 6;
        if (lid < 61) {
#pragma unroll
            for (int h0 = 0; h0 < 128; h0 += 4) {
                int h = h0 + rid;
                s[h][lid] = w1[(size_t)(hb * 128 + h) * FLAT + co * 61 + lid];
            }
        }
    }
    __syncthreads();
    {
        int h = tid & 127, ls = tid >> 7;     // ls 0..1
        for (int l = ls; l < 61; l += 2) {
            g_W1t[(size_t)(l * 64 + co) * H1 + hb * 128 + h] = __float2half_rn(s[h][l]);
        }
    }
}

// ===========================================================================
// prep_gemm: W12[n][k'=l*64+co] = sum_h fc2_w[n,h] * W1t[k'][h].
// Grid = 61 (one CTA per l). M=128(n), N=64(co), K=512 (8 chunks of 64 h).
// ===========================================================================
__global__ __launch_bounds__(256) void prep_gemm(const float* __restrict__ w2)
{
    __shared__ uint32_t As[128 * 36];   // [n][hp] half2
    __shared__ uint32_t Bs[64 * 36];    // [co][hp]

    const int tid = threadIdx.x, wid = tid >> 5, lane = tid & 31;
    const int g = lane >> 2, tig = lane & 3;
    const int mbase = (wid >> 1) * 32, nb = (wid & 1) * 32;
    const int l = blockIdx.x;

    float acc[2][4][4];
#pragma unroll
    for (int a = 0; a < 2; a++)
#pragma unroll
        for (int b = 0; b < 4; b++)
#pragma unroll
            for (int c2 = 0; c2 < 4; c2++) acc[a][b][c2] = 0.0f;

    for (int c = 0; c < 8; c++) {
        __syncthreads();
#pragma unroll
        for (int i = 0; i < 16; i++) {
            int u = tid + 256 * i;
            int n = u >> 5, hp = u & 31;
            float2 v = *(const float2*)(w2 + n * H1 + c * 64 + 2 * hp);
            As[n * 36 + hp] = packh2(v.x, v.y);
        }
#pragma unroll
        for (int i = 0; i < 8; i++) {
            int u = tid + 256 * i;
            int co = u >> 5, hp = u & 31;
            Bs[co * 36 + hp] = *(const uint32_t*)(g_W1t + (size_t)(l * 64 + co) * H1 + c * 64 + 2 * hp);
        }
        __syncthreads();
#pragma unroll
        for (int ks = 0; ks < 4; ks++) {
            uint32_t A[2][4], B[4][2];
#pragma unroll
            for (int mf = 0; mf < 2; mf++) {
                int r = mbase + 16 * mf + g;
                int wd = r * 36 + ks * 8 + tig;
                A[mf][0] = As[wd];          A[mf][1] = As[wd + 8 * 36];
                A[mf][2] = As[wd + 4];      A[mf][3] = As[wd + 8 * 36 + 4];
            }
#pragma unroll
            for (int nf = 0; nf < 4; nf++) {
                int n = nb + 8 * nf + g;
                int wd = n * 36 + ks * 8 + tig;
                B[nf][0] = Bs[wd]; B[nf][1] = Bs[wd + 4];
            }
#pragma unroll
            for (int mf = 0; mf < 2; mf++)
#pragma unroll
                for (int nf = 0; nf < 4; nf++)
                    mma16816(acc[mf][nf], A[mf], B[nf]);
        }
    }
#pragma unroll
    for (int nf = 0; nf < 4; nf++) {
        int c0 = nb + 8 * nf + 2 * tig;
#pragma unroll
        for (int mf = 0; mf < 2; mf++) {
            int r = mbase + 16 * mf + g;
            *(uint32_t*)(g_W12h + (size_t)r * FLAT + l * 64 + c0) =
                packh2(acc[mf][nf][0], acc[mf][nf][1]);
            *(uint32_t*)(g_W12h + (size_t)(r + 8) * FLAT + l * 64 + c0) =
                packh2(acc[mf][nf][2], acc[mf][nf][3]);
        }
    }
}

// ===========================================================================
// conv_mma2: Conv1d+BN+ReLU implicit-im2col GEMM, ldmatrix + 64x64 warp tiles.
// CTA = 4 batches (one per warp). M=256, N=64(co), K=4096 in chunks of 32.
// smem per buffer: 8 regions (bi,cih) x 288 words (xsA @0, xsB @144 for bank
// complement) + bs 64x20 words.  Ping-pong, one sync per chunk.
// A rows overlap 8B (stride-4 conv): even rows read aligned copy xsA, odd rows
// read 8B-shifted copy xsB -> conflict-free ldmatrix.
// ===========================================================================
#define CV_BUFW  (8 * 288 + 64 * 20)   // 3584 words = 14336 B
__global__ __launch_bounds__(128) void conv_mma2(const float* __restrict__ x)
{
    __shared__ uint32_t sm[2][CV_BUFW];

    const int tid = threadIdx.x, wid = tid >> 5, lane = tid & 31;
    const int g = lane >> 2, tig = lane & 3;
    const int b0 = blockIdx.x * 4;
    const uint32_t smb = cvta_sm(sm);

    float acc[4][8][4];
#pragma unroll
    for (int a = 0; a < 4; a++)
#pragma unroll
        for (int b = 0; b < 8; b++)
#pragma unroll
            for (int c2 = 0; c2 < 4; c2++) acc[a][b][c2] = 0.0f;

    // staging precompute (x): i 0..3: e = tid+128i -> bi,cih,t4i
    size_t xoff[4];
    int sA[4];
    bool doB[4];
#pragma unroll
    for (int i = 0; i < 4; i++) {
        int e = tid + 128 * i;
        int bi = e >> 7, cih = (e >> 6) & 1, t4i = e & 63;
        xoff[i] = (size_t)(b0 + bi) * 65536 + cih * 256 + 4 * t4i;
        sA[i] = (bi * 2 + cih) * 288 + 2 * t4i;
        doB[i] = (t4i >= 1);
    }
    // staging precompute (weights): i 0..1
    int woff[2], bso[2];
#pragma unroll
    for (int i = 0; i < 2; i++) {
        int u = tid + 128 * i;
        int co = u >> 2, q = u & 3;
        woff[i] = co * 4096 + q * 8;
        bso[i] = 8 * 288 + co * 20 + q * 4;
    }
    // ldmatrix A address components: per (ks, mf):
    // byte = region(wid*2+ks)*1152 + (lane&1)*576 + (8mf + (lane&15)/2 + lane/16)*16
    const uint32_t aoff = (lane & 1) * 576 + (((lane & 15) >> 1) + (lane >> 4)) * 16;
    // ldmatrix B address: word = (16q + nbt)*20 + ks*8 + koffw
    const int nbt = 8 * (lane >> 4) + (lane & 7);
    const uint32_t boffw = (uint32_t)(8 * 288 + nbt * 20 + ((lane >> 3) & 1) * 4);

    float4 xv[4];
    uint4  wv[2];

#define LDGX(cc) do { \
    _Pragma("unroll") for (int i = 0; i < 4; i++) \
        xv[i] = *(const float4*)(x + xoff[i] + (size_t)(cc) * 512); \
    _Pragma("unroll") for (int i = 0; i < 2; i++) \
        wv[i] = *(const uint4*)(g_WcH + woff[i] + (cc) * 32); \
} while (0)

#define STSX(bf) do { \
    uint32_t* B_ = sm[bf]; \
    _Pragma("unroll") for (int i = 0; i < 4; i++) { \
        uint32_t h0 = packh2(xv[i].x, xv[i].y); \
        uint32_t h1 = packh2(xv[i].z, xv[i].w); \
        *(uint2*)&B_[sA[i]] = make_uint2(h0, h1); \
        if (doB[i]) *(uint2*)&B_[sA[i] + 142] = make_uint2(h0, h1); \
    } \
    _Pragma("unroll") for (int i = 0; i < 2; i++) \
        *(uint4*)&B_[bso[i]] = wv[i]; \
} while (0)

    // preamble
    LDGX(0);
    STSX(0);
    LDGX(1);
    __syncthreads();

#pragma unroll 1
    for (int c = 0; c < 128; c++) {
        const int buf = c & 1;
        if (c < 127) STSX(buf ^ 1);
        if (c < 126) LDGX(c + 2);

        const uint32_t bb = smb + buf * (CV_BUFW * 4);
#pragma unroll
        for (int ks = 0; ks < 2; ks++) {
            uint32_t A[4][4], B[8][2];
            const uint32_t abase = bb + (uint32_t)((wid * 2 + ks) * 1152) + aoff;
#pragma unroll
            for (int mf = 0; mf < 4; mf++) ldsm4(A[mf], abase + mf * 128);
            const uint32_t bbase = bb + (boffw + ks * 8) * 4;
#pragma unroll
            for (int q = 0; q < 4; q++) {
                uint32_t r[4];
                ldsm4(r, bbase + (uint32_t)(16 * q * 20) * 4);
                B[2 * q][0] = r[0]; B[2 * q][1] = r[1];
                B[2 * q + 1][0] = r[2]; B[2 * q + 1][1] = r[3];
            }
#pragma unroll
            for (int mf = 0; mf < 4; mf++)
#pragma unroll
                for (int nf = 0; nf < 8; nf++)
                    mma16816(acc[mf][nf], A[mf], B[nf]);
        }
        __syncthreads();
    }

    // epilogue: warp = batch b0+wid, rows lp = 16mf+g (+8)
    const size_t obase = (size_t)(b0 + wid) * FLAT;
#pragma unroll
    for (int nf = 0; nf < 8; nf++) {
        int co = 8 * nf + 2 * tig;
        float s0 = g_bshift[co], s1 = g_bshift[co + 1];
#pragma unroll
        for (int mf = 0; mf < 4; mf++) {
            int lp0 = 16 * mf + g;
            if (lp0 < 61)
                *(uint32_t*)(g_actH + obase + lp0 * 64 + co) =
                    packh2(fmaxf(acc[mf][nf][0] + s0, 0.0f),
                           fmaxf(acc[mf][nf][1] + s1, 0.0f));
            int lp1 = lp0 + 8;
            if (lp1 < 61)
                *(uint32_t*)(g_actH + obase + lp1 * 64 + co) =
                    packh2(fmaxf(acc[mf][nf][2] + s0, 0.0f),
                           fmaxf(acc[mf][nf][3] + s1, 0.0f));
        }
    }
#undef LDGX
#undef STSX
}

// ===========================================================================
// fc_part: split-K fused FC.  part[ks][b][n] = act[b,:] . W12[n,:] (K slice)
// ===========================================================================
__global__ __launch_bounds__(256, 2) void fc_part()
{
    __shared__ uint32_t As[128 * 36];
    __shared__ uint32_t Bs[128 * 36];

    const int tid = threadIdx.x, wid = tid >> 5, lane = tid & 31;
    const int g = lane >> 2, tig = lane & 3;
    const int mbase = (wid >> 1) * 32, nbase = (wid & 1) * 64;
    const int m0 = blockIdx.x * 128;
    const int ksp = blockIdx.y;
    const int cb = (61 * ksp) / 8, ce = (61 * (ksp + 1)) / 8;

    float acc[2][8][4];
#pragma unroll
    for (int a = 0; a < 2; a++)
#pragma unroll
        for (int b = 0; b < 8; b++)
#pragma unroll
            for (int c2 = 0; c2 < 4; c2++) acc[a][b][c2] = 0.0f;

    for (int c = cb; c < ce; c++) {
        __syncthreads();
#pragma unroll
        for (int i = 0; i < 4; i++) {
            int u = tid + 256 * i;
            int row = u >> 3, q = u & 7;
            uint4 av = *(const uint4*)(g_actH + (size_t)(m0 + row) * FLAT + c * 64 + q * 8);
            uint4 bv = *(const uint4*)(g_W12h + (size_t)row * FLAT + c * 64 + q * 8);
            *(uint4*)&As[row * 36 + q * 4] = av;
            *(uint4*)&Bs[row * 36 + q * 4] = bv;
        }
        __syncthreads();
#pragma unroll
        for (int ks = 0; ks < 4; ks++) {
            uint32_t A[2][4], B[8][2];
#pragma unroll
            for (int mf = 0; mf < 2; mf++) {
                int r = mbase + 16 * mf + g;
                int wd = r * 36 + ks * 8 + tig;
                A[mf][0] = As[wd];       A[mf][1] = As[wd + 8 * 36];
                A[mf][2] = As[wd + 4];   A[mf][3] = As[wd + 8 * 36 + 4];
            }
#pragma unroll
            for (int nf = 0; nf < 8; nf++) {
                int n = nbase + 8 * nf + g;
                int wd = n * 36 + ks * 8 + tig;
                B[nf][0] = Bs[wd]; B[nf][1] = Bs[wd + 4];
            }
#pragma unroll
            for (int mf = 0; mf < 2; mf++)
#pragma unroll
                for (int nf = 0; nf < 8; nf++)
                    mma16816(acc[mf][nf], A[mf], B[nf]);
        }
    }
#pragma unroll
    for (int nf = 0; nf < 8; nf++) {
        int c0 = nbase + 8 * nf + 2 * tig;
#pragma unroll
        for (int mf = 0; mf < 2; mf++) {
            int r = mbase + 16 * mf + g;
            *(float2*)(g_part + ((size_t)ksp * BATCH + m0 + r) * H2 + c0) =
                make_float2(acc[mf][nf][0], acc[mf][nf][1]);
            *(float2*)(g_part + ((size_t)ksp * BATCH + m0 + r + 8) * H2 + c0) =
                make_float2(acc[mf][nf][2], acc[mf][nf][3]);
        }
    }
}

// ===========================================================================
// fc_reduce: sum split-K partials + b12, apply parabit heads.
// ===========================================================================
__global__ void fc_reduce(const float* __restrict__ bw, const float* __restrict__ bb,
                          float* __restrict__ out)
{
    int idx = blockIdx.x * blockDim.x + threadIdx.x;
    int n = idx & 127;
    float s = g_b12[n];
#pragma unroll
    for (int ks = 0; ks < 8; ks++)
        s += g_part[(size_t)ks * BATCH * H2 + idx];
    float2 o = make_float2(fmaf(s, bw[2 * n], bb[2 * n]),
                           fmaf(s, bw[2 * n + 1], bb[2 * n + 1]));
    *(float2*)(out + (size_t)idx * 2) = o;
}

// ===========================================================================
extern "C" void kernel_launch(void* const* d_in, const int* in_sizes, int n_in,
                              void* d_out, int out_size)
{
    const float* x      = (const float*)d_in[0];
    const float* conv_w = (const float*)d_in[1];
    const float* conv_b = (const float*)d_in[2];
    const float* bn_g   = (const float*)d_in[3];
    const float* bn_b   = (const float*)d_in[4];
    const float* bn_m   = (const float*)d_in[5];
    const float* bn_v   = (const float*)d_in[6];
    const float* fc1_w  = (const float*)d_in[7];
    const float* fc1_b  = (const float*)d_in[8];
    const float* fc2_w  = (const float*)d_in[9];
    const float* fc2_b  = (const float*)d_in[10];
    const float* bit_w  = (const float*)d_in[11];
    const float* bit_b  = (const float*)d_in[12];
    float* out = (float*)d_out;

    prep_split<<<256, 256>>>(conv_w, conv_b, bn_g, bn_b, bn_m, bn_v);
    prep_b12<<<16, 256>>>(fc2_w, fc1_b, fc2_b);
    transpose_w1<<<dim3(64, 4), 256>>>(fc1_w);
    prep_gemm<<<61, 256>>>(fc2_w);
    conv_mma2<<<BATCH / 4, 128>>>(x);
    fc_part<<<dim3(16, 8), 256>>>();
    fc_reduce<<<BATCH * H2 / 256, 256>>>(bit_w, bit_b, out);
}